// round 6
// baseline (speedup 1.0000x reference)
#include <cuda_runtime.h>
#include <math.h>

// x: (8,4096,512) -> N=32768, D=512 ; embed: (1,8192,512) -> C=8192
// Outputs (float32, concatenated in d_out):
//   quantize 16,777,216 | embed_ind 32,768 | new_embed 4,194,304 | new_cs 8,192

#define N_TOK   32768
#define C_CODES 8192
#define D_DIM   512
#define ONE_MINUS_DECAY 0.2f

// -------- device scratch ----------------------------------------------------
__device__ float g_embed_n[C_CODES * D_DIM];   // normalized codebook (16 MB)
__device__ float g_xn[N_TOK * D_DIM];          // normalized tokens   (64 MB)
__device__ float g_embed_sum[C_CODES * D_DIM]; // EMA numerator scatter
__device__ float g_bins[C_CODES];
__device__ int   g_ind[N_TOK];

// -------- helpers -----------------------------------------------------------
__device__ __forceinline__ float block_reduce_sum_128(float v) {
    #pragma unroll
    for (int o = 16; o > 0; o >>= 1) v += __shfl_xor_sync(0xffffffffu, v, o);
    __shared__ float sp[4];
    int w = threadIdx.x >> 5, l = threadIdx.x & 31;
    if (l == 0) sp[w] = v;
    __syncthreads();
    if (threadIdx.x == 0) sp[0] = sp[0] + sp[1] + sp[2] + sp[3];
    __syncthreads();
    return sp[0];
}

// Reference-faithful row sum-of-squares (XLA:CPU aarch64 VF=4 IC=2 order):
// 8 interleaved fma chains over stride-8 lanes, lanewise add, pairwise tree.
__device__ __forceinline__ float mimic_sumsq_512(const float* __restrict__ s) {
    float p0 = 0.f, p1 = 0.f, p2 = 0.f, p3 = 0.f;
    float p4 = 0.f, p5 = 0.f, p6 = 0.f, p7 = 0.f;
    #pragma unroll 4
    for (int j = 0; j < D_DIM; j += 8) {
        p0 = fmaf(s[j + 0], s[j + 0], p0);
        p1 = fmaf(s[j + 1], s[j + 1], p1);
        p2 = fmaf(s[j + 2], s[j + 2], p2);
        p3 = fmaf(s[j + 3], s[j + 3], p3);
        p4 = fmaf(s[j + 4], s[j + 4], p4);
        p5 = fmaf(s[j + 5], s[j + 5], p5);
        p6 = fmaf(s[j + 6], s[j + 6], p6);
        p7 = fmaf(s[j + 7], s[j + 7], p7);
    }
    float v0 = p0 + p4, v1 = p1 + p5, v2 = p2 + p6, v3 = p3 + p7;
    return (v0 + v2) + (v1 + v3);
}

// ============================================================================
// Kernel 1: normalize codebook rows (sqrt(sumsq), clip, IEEE fp32 DIVISION).
// ============================================================================
__global__ void norm_embed_kernel(const float* __restrict__ embed) {
    __shared__ float srow[D_DIM];
    __shared__ float s_norm;
    int c = blockIdx.x;
    int t = threadIdx.x;
    float4 e = reinterpret_cast<const float4*>(embed + (size_t)c * D_DIM)[t];
    reinterpret_cast<float4*>(srow)[t] = e;
    __syncthreads();
    if (t == 0) {
        float nrm = sqrtf(mimic_sumsq_512(srow));
        if (nrm < 1e-12f) nrm = 1e-12f;
        s_norm = nrm;
    }
    __syncthreads();
    float nrm = s_norm;
    reinterpret_cast<float4*>(g_embed_n + (size_t)c * D_DIM)[t] =
        make_float4(__fdiv_rn(e.x, nrm), __fdiv_rn(e.y, nrm),
                    __fdiv_rn(e.z, nrm), __fdiv_rn(e.w, nrm));
    reinterpret_cast<float4*>(g_embed_sum + (size_t)c * D_DIM)[t] =
        make_float4(0.f, 0.f, 0.f, 0.f);
    if (t == 0) g_bins[c] = 0.f;
}

// ============================================================================
// Kernel 1b: normalize tokens (same arithmetic).
// ============================================================================
__global__ void norm_x_kernel(const float* __restrict__ X) {
    __shared__ float srow[D_DIM];
    __shared__ float s_norm;
    int n = blockIdx.x;
    int t = threadIdx.x;
    float4 xv = reinterpret_cast<const float4*>(X + (size_t)n * D_DIM)[t];
    reinterpret_cast<float4*>(srow)[t] = xv;
    __syncthreads();
    if (t == 0) {
        float nrm = sqrtf(mimic_sumsq_512(srow));
        if (nrm < 1e-12f) nrm = 1e-12f;
        s_norm = nrm;
    }
    __syncthreads();
    float nrm = s_norm;
    reinterpret_cast<float4*>(g_xn + (size_t)n * D_DIM)[t] =
        make_float4(__fdiv_rn(xv.x, nrm), __fdiv_rn(xv.y, nrm),
                    __fdiv_rn(xv.z, nrm), __fdiv_rn(xv.w, nrm));
}

// ============================================================================
// Kernel 2: fused fp32 GEMM + row argmax, packed fma.rn.f32x2 engine.
// Bit-exact vs scalar FFMA version: each output element keeps a single
// sequential-k IEEE fp32 fma chain (one f32x2 lane).
//   - As stored DUPLICATED (a,a) pairs -> broadcast pairs load pre-packed
//   - Bs adjacent columns form natural (b_j, b_j+1) pairs
// BM=BN=128, BK=16, 256 thr, 8x8 microtile (as 8x4 f32x2 pairs).
// ============================================================================
#define BM 128
#define BN 128
#define BK 16

__global__ __launch_bounds__(256, 2)
void argmax_kernel() {
    __shared__ float As[BK][2 * BM];   // duplicated (a,a) pairs: 16 KB
    __shared__ float Bs[BK][BN];       // 8 KB
    __shared__ float s_val[BM][16];
    __shared__ int   s_idx[BM][16];

    const int tid  = threadIdx.x;
    const int tcol = tid & 15;
    const int trow = tid >> 4;
    const int m0 = trow * 8;
    const int n0 = tcol * 8;
    const int rowBase = blockIdx.x * BM;
    const float* __restrict__ XN = g_xn;
    const float* __restrict__ EN = g_embed_n;

    const int lr = tid >> 2;          // 0..63
    const int lc = (tid & 3) * 4;     // 0,4,8,12

    float bestv[8];
    int   besti[8];
    #pragma unroll
    for (int i = 0; i < 8; i++) { bestv[i] = -3.4e38f; besti[i] = 0; }

    for (int nt = 0; nt < C_CODES / BN; nt++) {
        const int colBase = nt * BN;
        unsigned long long acc2[8][4];
        #pragma unroll
        for (int i = 0; i < 8; i++)
            #pragma unroll
            for (int jp = 0; jp < 4; jp++) acc2[i][jp] = 0ull;

        for (int kt = 0; kt < D_DIM / BK; kt++) {
            const int k0 = kt * BK;
            // ---- load A tile (x rows) as duplicated pairs: As[k][2m]=As[k][2m+1]=a
            {
                const float* p0 = XN + (size_t)(rowBase + lr) * D_DIM + k0 + lc;
                const float* p1 = p0 + (size_t)64 * D_DIM;
                float4 a0 = *reinterpret_cast<const float4*>(p0);
                float4 a1 = *reinterpret_cast<const float4*>(p1);
                *reinterpret_cast<float2*>(&As[lc + 0][2 * lr]) = make_float2(a0.x, a0.x);
                *reinterpret_cast<float2*>(&As[lc + 1][2 * lr]) = make_float2(a0.y, a0.y);
                *reinterpret_cast<float2*>(&As[lc + 2][2 * lr]) = make_float2(a0.z, a0.z);
                *reinterpret_cast<float2*>(&As[lc + 3][2 * lr]) = make_float2(a0.w, a0.w);
                *reinterpret_cast<float2*>(&As[lc + 0][2 * (lr + 64)]) = make_float2(a1.x, a1.x);
                *reinterpret_cast<float2*>(&As[lc + 1][2 * (lr + 64)]) = make_float2(a1.y, a1.y);
                *reinterpret_cast<float2*>(&As[lc + 2][2 * (lr + 64)]) = make_float2(a1.z, a1.z);
                *reinterpret_cast<float2*>(&As[lc + 3][2 * (lr + 64)]) = make_float2(a1.w, a1.w);
            }
            // ---- load B tile (embed_n rows), transposed into Bs[k][n]
            {
                const float* p0 = EN + (size_t)(colBase + lr) * D_DIM + k0 + lc;
                const float* p1 = p0 + (size_t)64 * D_DIM;
                float4 b0 = *reinterpret_cast<const float4*>(p0);
                float4 b1 = *reinterpret_cast<const float4*>(p1);
                Bs[lc + 0][lr] = b0.x; Bs[lc + 1][lr] = b0.y;
                Bs[lc + 2][lr] = b0.z; Bs[lc + 3][lr] = b0.w;
                Bs[lc + 0][lr + 64] = b1.x; Bs[lc + 1][lr + 64] = b1.y;
                Bs[lc + 2][lr + 64] = b1.z; Bs[lc + 3][lr + 64] = b1.w;
            }
            __syncthreads();

            #pragma unroll
            for (int k = 0; k < BK; k++) {
                const ulonglong2* ap =
                    reinterpret_cast<const ulonglong2*>(&As[k][2 * m0]);
                ulonglong2 A01 = ap[0], A23 = ap[1], A45 = ap[2], A67 = ap[3];
                unsigned long long a2[8] = {A01.x, A01.y, A23.x, A23.y,
                                            A45.x, A45.y, A67.x, A67.y};
                const ulonglong2* bp =
                    reinterpret_cast<const ulonglong2*>(&Bs[k][n0]);
                ulonglong2 B01 = bp[0], B23 = bp[1];
                unsigned long long b2[4] = {B01.x, B01.y, B23.x, B23.y};
                #pragma unroll
                for (int i = 0; i < 8; i++)
                    #pragma unroll
                    for (int jp = 0; jp < 4; jp++)
                        asm("fma.rn.f32x2 %0, %1, %2, %0;"
                            : "+l"(acc2[i][jp]) : "l"(a2[i]), "l"(b2[jp]));
            }
            __syncthreads();
        }

        // fold tile into running best (ascending c -> first-index on exact tie)
        #pragma unroll
        for (int jp = 0; jp < 4; jp++) {
            #pragma unroll
            for (int i = 0; i < 8; i++) {
                float lo, hi;
                asm("mov.b64 {%0, %1}, %2;" : "=f"(lo), "=f"(hi) : "l"(acc2[i][jp]));
                const int c0 = colBase + n0 + 2 * jp;
                if (lo > bestv[i]) { bestv[i] = lo; besti[i] = c0; }
                if (hi > bestv[i]) { bestv[i] = hi; besti[i] = c0 + 1; }
            }
        }
    }

    #pragma unroll
    for (int i = 0; i < 8; i++) {
        s_val[m0 + i][tcol] = bestv[i];
        s_idx[m0 + i][tcol] = besti[i];
    }
    __syncthreads();
    if (tid < BM) {
        float bv = -3.4e38f; int bi = 0x7fffffff;
        #pragma unroll
        for (int t = 0; t < 16; t++) {
            float v  = s_val[tid][t];
            int   ix = s_idx[tid][t];
            if (v > bv || (v == bv && ix < bi)) { bv = v; bi = ix; }
        }
        g_ind[rowBase + tid] = bi;
    }
}

// ============================================================================
// Kernel 3: per-token epilogue (gather quantize, scatter normalized x + bins).
// ============================================================================
__global__ void epilogue_kernel(const float* __restrict__ embed,
                                float* __restrict__ out_q,
                                float* __restrict__ out_ind) {
    int n = blockIdx.x;
    int t = threadIdx.x;
    int c = g_ind[n];

    float4 xn = reinterpret_cast<const float4*>(g_xn + (size_t)n * D_DIM)[t];
    float* es = g_embed_sum + (size_t)c * D_DIM + t * 4;
    atomicAdd(es + 0, xn.x);
    atomicAdd(es + 1, xn.y);
    atomicAdd(es + 2, xn.z);
    atomicAdd(es + 3, xn.w);

    float4 ev = reinterpret_cast<const float4*>(embed + (size_t)c * D_DIM)[t];
    reinterpret_cast<float4*>(out_q + (size_t)n * D_DIM)[t] = ev;

    if (t == 0) {
        out_ind[n] = (float)c;
        atomicAdd(&g_bins[c], 1.0f);
    }
}

// ============================================================================
// Kernel 4: per-code EMA finalize.
// ============================================================================
__global__ void finalize_kernel(const float* __restrict__ embed,
                                const float* __restrict__ cluster_size,
                                float* __restrict__ out_embed,
                                float* __restrict__ out_cs) {
    int c = blockIdx.x;
    int t = threadIdx.x;
    float b = g_bins[c];
    bool zero = (b == 0.0f);
    float inv_b = 1.0f / (zero ? 1.0f : b);

    float4 es = reinterpret_cast<const float4*>(g_embed_sum + (size_t)c * D_DIM)[t];
    float4 v = make_float4(es.x * inv_b, es.y * inv_b, es.z * inv_b, es.w * inv_b);
    float ss = v.x * v.x + v.y * v.y + v.z * v.z + v.w * v.w;
    ss = block_reduce_sum_128(ss);
    float rn = 1.0f / fmaxf(sqrtf(ss), 1e-12f);

    float4 en;
    if (zero) en = reinterpret_cast<const float4*>(g_embed_n + (size_t)c * D_DIM)[t];
    else      en = make_float4(v.x * rn, v.y * rn, v.z * rn, v.w * rn);

    float4 e = reinterpret_cast<const float4*>(embed + (size_t)c * D_DIM)[t];
    reinterpret_cast<float4*>(out_embed + (size_t)c * D_DIM)[t] =
        make_float4(e.x + ONE_MINUS_DECAY * (en.x - e.x),
                    e.y + ONE_MINUS_DECAY * (en.y - e.y),
                    e.z + ONE_MINUS_DECAY * (en.z - e.z),
                    e.w + ONE_MINUS_DECAY * (en.w - e.w));

    if (t == 0) {
        float cs = cluster_size[c];
        out_cs[c] = cs + ONE_MINUS_DECAY * (b - cs);
    }
}

// ============================================================================
extern "C" void kernel_launch(void* const* d_in, const int* in_sizes, int n_in,
                              void* d_out, int out_size) {
    const float* x     = (const float*)d_in[0];
    const float* embed = (const float*)d_in[1];
    const float* cs    = (const float*)d_in[2];

    float* out       = (float*)d_out;
    float* out_q     = out;
    float* out_ind   = out + 16777216;
    float* out_embed = out + 16777216 + 32768;
    float* out_cs    = out + 16777216 + 32768 + 4194304;

    norm_embed_kernel<<<C_CODES, 128>>>(embed);
    norm_x_kernel<<<N_TOK, 128>>>(x);
    argmax_kernel<<<N_TOK / BM, 256>>>();
    epilogue_kernel<<<N_TOK, 128>>>(embed, out_q, out_ind);
    finalize_kernel<<<C_CODES, 128>>>(embed, cs, out_embed, out_cs);
}

// round 7
// speedup vs baseline: 1.0015x; 1.0015x over previous
#include <cuda_runtime.h>
#include <math.h>

// x: (8,4096,512) -> N=32768, D=512 ; embed: (1,8192,512) -> C=8192
// Outputs (float32, concatenated in d_out):
//   quantize 16,777,216 | embed_ind 32,768 | new_embed 4,194,304 | new_cs 8,192

#define N_TOK   32768
#define C_CODES 8192
#define D_DIM   512
#define ONE_MINUS_DECAY 0.2f

// -------- device scratch ----------------------------------------------------
__device__ float g_embed_n[C_CODES * D_DIM];   // normalized codebook (16 MB)
__device__ float g_xn[N_TOK * D_DIM];          // normalized tokens   (64 MB)
__device__ float g_embed_sum[C_CODES * D_DIM]; // EMA numerator scatter
__device__ float g_bins[C_CODES];
__device__ int   g_ind[N_TOK];

// -------- helpers -----------------------------------------------------------
__device__ __forceinline__ float block_reduce_sum_128(float v) {
    #pragma unroll
    for (int o = 16; o > 0; o >>= 1) v += __shfl_xor_sync(0xffffffffu, v, o);
    __shared__ float sp[4];
    int w = threadIdx.x >> 5, l = threadIdx.x & 31;
    if (l == 0) sp[w] = v;
    __syncthreads();
    if (threadIdx.x == 0) sp[0] = sp[0] + sp[1] + sp[2] + sp[3];
    __syncthreads();
    return sp[0];
}

// Reference-faithful row sum-of-squares (XLA:CPU aarch64 VF=4 IC=2 order):
// 8 interleaved fma chains over stride-8 lanes, lanewise add, pairwise tree.
__device__ __forceinline__ float mimic_sumsq_512(const float* __restrict__ s) {
    float p0 = 0.f, p1 = 0.f, p2 = 0.f, p3 = 0.f;
    float p4 = 0.f, p5 = 0.f, p6 = 0.f, p7 = 0.f;
    #pragma unroll 4
    for (int j = 0; j < D_DIM; j += 8) {
        p0 = fmaf(s[j + 0], s[j + 0], p0);
        p1 = fmaf(s[j + 1], s[j + 1], p1);
        p2 = fmaf(s[j + 2], s[j + 2], p2);
        p3 = fmaf(s[j + 3], s[j + 3], p3);
        p4 = fmaf(s[j + 4], s[j + 4], p4);
        p5 = fmaf(s[j + 5], s[j + 5], p5);
        p6 = fmaf(s[j + 6], s[j + 6], p6);
        p7 = fmaf(s[j + 7], s[j + 7], p7);
    }
    float v0 = p0 + p4, v1 = p1 + p5, v2 = p2 + p6, v3 = p3 + p7;
    return (v0 + v2) + (v1 + v3);
}

// ============================================================================
// Kernel 1: normalize codebook rows (sqrt(sumsq), clip, IEEE fp32 DIVISION).
// ============================================================================
__global__ void norm_embed_kernel(const float* __restrict__ embed) {
    __shared__ float srow[D_DIM];
    __shared__ float s_norm;
    int c = blockIdx.x;
    int t = threadIdx.x;
    float4 e = reinterpret_cast<const float4*>(embed + (size_t)c * D_DIM)[t];
    reinterpret_cast<float4*>(srow)[t] = e;
    __syncthreads();
    if (t == 0) {
        float nrm = sqrtf(mimic_sumsq_512(srow));
        if (nrm < 1e-12f) nrm = 1e-12f;
        s_norm = nrm;
    }
    __syncthreads();
    float nrm = s_norm;
    reinterpret_cast<float4*>(g_embed_n + (size_t)c * D_DIM)[t] =
        make_float4(__fdiv_rn(e.x, nrm), __fdiv_rn(e.y, nrm),
                    __fdiv_rn(e.z, nrm), __fdiv_rn(e.w, nrm));
    reinterpret_cast<float4*>(g_embed_sum + (size_t)c * D_DIM)[t] =
        make_float4(0.f, 0.f, 0.f, 0.f);
    if (t == 0) g_bins[c] = 0.f;
}

// ============================================================================
// Kernel 1b: normalize tokens (same arithmetic).
// ============================================================================
__global__ void norm_x_kernel(const float* __restrict__ X) {
    __shared__ float srow[D_DIM];
    __shared__ float s_norm;
    int n = blockIdx.x;
    int t = threadIdx.x;
    float4 xv = reinterpret_cast<const float4*>(X + (size_t)n * D_DIM)[t];
    reinterpret_cast<float4*>(srow)[t] = xv;
    __syncthreads();
    if (t == 0) {
        float nrm = sqrtf(mimic_sumsq_512(srow));
        if (nrm < 1e-12f) nrm = 1e-12f;
        s_norm = nrm;
    }
    __syncthreads();
    float nrm = s_norm;
    reinterpret_cast<float4*>(g_xn + (size_t)n * D_DIM)[t] =
        make_float4(__fdiv_rn(xv.x, nrm), __fdiv_rn(xv.y, nrm),
                    __fdiv_rn(xv.z, nrm), __fdiv_rn(xv.w, nrm));
}

// ============================================================================
// Kernel 2: fused fp32 GEMM + row argmax, packed fma.rn.f32x2 engine.
// Bit-exact vs scalar FFMA version: each output element keeps a single
// sequential-k IEEE fp32 fma chain (one f32x2 lane).
//   - As stored DUPLICATED (a,a) pairs -> broadcast pairs load pre-packed
//   - Bs adjacent columns form natural (b_j, b_j+1) pairs
// BM=BN=128, BK=16, 256 thr, 8x8 microtile (as 8x4 f32x2 pairs).
// ============================================================================
#define BM 128
#define BN 128
#define BK 16

__global__ __launch_bounds__(256, 2)
void argmax_kernel() {
    __shared__ float As[BK][2 * BM];   // duplicated (a,a) pairs: 16 KB
    __shared__ float Bs[BK][BN];       // 8 KB
    __shared__ float s_val[BM][16];
    __shared__ int   s_idx[BM][16];

    const int tid  = threadIdx.x;
    const int tcol = tid & 15;
    const int trow = tid >> 4;
    const int m0 = trow * 8;
    const int n0 = tcol * 8;
    const int rowBase = blockIdx.x * BM;
    const float* __restrict__ XN = g_xn;
    const float* __restrict__ EN = g_embed_n;

    const int lr = tid >> 2;          // 0..63
    const int lc = (tid & 3) * 4;     // 0,4,8,12

    float bestv[8];
    int   besti[8];
    #pragma unroll
    for (int i = 0; i < 8; i++) { bestv[i] = -3.4e38f; besti[i] = 0; }

    for (int nt = 0; nt < C_CODES / BN; nt++) {
        const int colBase = nt * BN;
        unsigned long long acc2[8][4];
        #pragma unroll
        for (int i = 0; i < 8; i++)
            #pragma unroll
            for (int jp = 0; jp < 4; jp++) acc2[i][jp] = 0ull;

        for (int kt = 0; kt < D_DIM / BK; kt++) {
            const int k0 = kt * BK;
            // ---- load A tile (x rows) as duplicated pairs: As[k][2m]=As[k][2m+1]=a
            {
                const float* p0 = XN + (size_t)(rowBase + lr) * D_DIM + k0 + lc;
                const float* p1 = p0 + (size_t)64 * D_DIM;
                float4 a0 = *reinterpret_cast<const float4*>(p0);
                float4 a1 = *reinterpret_cast<const float4*>(p1);
                *reinterpret_cast<float2*>(&As[lc + 0][2 * lr]) = make_float2(a0.x, a0.x);
                *reinterpret_cast<float2*>(&As[lc + 1][2 * lr]) = make_float2(a0.y, a0.y);
                *reinterpret_cast<float2*>(&As[lc + 2][2 * lr]) = make_float2(a0.z, a0.z);
                *reinterpret_cast<float2*>(&As[lc + 3][2 * lr]) = make_float2(a0.w, a0.w);
                *reinterpret_cast<float2*>(&As[lc + 0][2 * (lr + 64)]) = make_float2(a1.x, a1.x);
                *reinterpret_cast<float2*>(&As[lc + 1][2 * (lr + 64)]) = make_float2(a1.y, a1.y);
                *reinterpret_cast<float2*>(&As[lc + 2][2 * (lr + 64)]) = make_float2(a1.z, a1.z);
                *reinterpret_cast<float2*>(&As[lc + 3][2 * (lr + 64)]) = make_float2(a1.w, a1.w);
            }
            // ---- load B tile (embed_n rows), transposed into Bs[k][n]
            {
                const float* p0 = EN + (size_t)(colBase + lr) * D_DIM + k0 + lc;
                const float* p1 = p0 + (size_t)64 * D_DIM;
                float4 b0 = *reinterpret_cast<const float4*>(p0);
                float4 b1 = *reinterpret_cast<const float4*>(p1);
                Bs[lc + 0][lr] = b0.x; Bs[lc + 1][lr] = b0.y;
                Bs[lc + 2][lr] = b0.z; Bs[lc + 3][lr] = b0.w;
                Bs[lc + 0][lr + 64] = b1.x; Bs[lc + 1][lr + 64] = b1.y;
                Bs[lc + 2][lr + 64] = b1.z; Bs[lc + 3][lr + 64] = b1.w;
            }
            __syncthreads();

            #pragma unroll
            for (int k = 0; k < BK; k++) {
                const ulonglong2* ap =
                    reinterpret_cast<const ulonglong2*>(&As[k][2 * m0]);
                ulonglong2 A01 = ap[0], A23 = ap[1], A45 = ap[2], A67 = ap[3];
                unsigned long long a2[8] = {A01.x, A01.y, A23.x, A23.y,
                                            A45.x, A45.y, A67.x, A67.y};
                const ulonglong2* bp =
                    reinterpret_cast<const ulonglong2*>(&Bs[k][n0]);
                ulonglong2 B01 = bp[0], B23 = bp[1];
                unsigned long long b2[4] = {B01.x, B01.y, B23.x, B23.y};
                #pragma unroll
                for (int i = 0; i < 8; i++)
                    #pragma unroll
                    for (int jp = 0; jp < 4; jp++)
                        asm("fma.rn.f32x2 %0, %1, %2, %0;"
                            : "+l"(acc2[i][jp]) : "l"(a2[i]), "l"(b2[jp]));
            }
            __syncthreads();
        }

        // fold tile into running best (ascending c -> first-index on exact tie)
        #pragma unroll
        for (int jp = 0; jp < 4; jp++) {
            #pragma unroll
            for (int i = 0; i < 8; i++) {
                float lo, hi;
                asm("mov.b64 {%0, %1}, %2;" : "=f"(lo), "=f"(hi) : "l"(acc2[i][jp]));
                const int c0 = colBase + n0 + 2 * jp;
                if (lo > bestv[i]) { bestv[i] = lo; besti[i] = c0; }
                if (hi > bestv[i]) { bestv[i] = hi; besti[i] = c0 + 1; }
            }
        }
    }

    #pragma unroll
    for (int i = 0; i < 8; i++) {
        s_val[m0 + i][tcol] = bestv[i];
        s_idx[m0 + i][tcol] = besti[i];
    }
    __syncthreads();
    if (tid < BM) {
        float bv = -3.4e38f; int bi = 0x7fffffff;
        #pragma unroll
        for (int t = 0; t < 16; t++) {
            float v  = s_val[tid][t];
            int   ix = s_idx[tid][t];
            if (v > bv || (v == bv && ix < bi)) { bv = v; bi = ix; }
        }
        g_ind[rowBase + tid] = bi;
    }
}

// ============================================================================
// Kernel 3: per-token epilogue (gather quantize, scatter normalized x + bins).
// ============================================================================
__global__ void epilogue_kernel(const float* __restrict__ embed,
                                float* __restrict__ out_q,
                                float* __restrict__ out_ind) {
    int n = blockIdx.x;
    int t = threadIdx.x;
    int c = g_ind[n];

    float4 xn = reinterpret_cast<const float4*>(g_xn + (size_t)n * D_DIM)[t];
    float* es = g_embed_sum + (size_t)c * D_DIM + t * 4;
    atomicAdd(es + 0, xn.x);
    atomicAdd(es + 1, xn.y);
    atomicAdd(es + 2, xn.z);
    atomicAdd(es + 3, xn.w);

    float4 ev = reinterpret_cast<const float4*>(embed + (size_t)c * D_DIM)[t];
    reinterpret_cast<float4*>(out_q + (size_t)n * D_DIM)[t] = ev;

    if (t == 0) {
        out_ind[n] = (float)c;
        atomicAdd(&g_bins[c], 1.0f);
    }
}

// ============================================================================
// Kernel 4: per-code EMA finalize.
// ============================================================================
__global__ void finalize_kernel(const float* __restrict__ embed,
                                const float* __restrict__ cluster_size,
                                float* __restrict__ out_embed,
                                float* __restrict__ out_cs) {
    int c = blockIdx.x;
    int t = threadIdx.x;
    float b = g_bins[c];
    bool zero = (b == 0.0f);
    float inv_b = 1.0f / (zero ? 1.0f : b);

    float4 es = reinterpret_cast<const float4*>(g_embed_sum + (size_t)c * D_DIM)[t];
    float4 v = make_float4(es.x * inv_b, es.y * inv_b, es.z * inv_b, es.w * inv_b);
    float ss = v.x * v.x + v.y * v.y + v.z * v.z + v.w * v.w;
    ss = block_reduce_sum_128(ss);
    float rn = 1.0f / fmaxf(sqrtf(ss), 1e-12f);

    float4 en;
    if (zero) en = reinterpret_cast<const float4*>(g_embed_n + (size_t)c * D_DIM)[t];
    else      en = make_float4(v.x * rn, v.y * rn, v.z * rn, v.w * rn);

    float4 e = reinterpret_cast<const float4*>(embed + (size_t)c * D_DIM)[t];
    reinterpret_cast<float4*>(out_embed + (size_t)c * D_DIM)[t] =
        make_float4(e.x + ONE_MINUS_DECAY * (en.x - e.x),
                    e.y + ONE_MINUS_DECAY * (en.y - e.y),
                    e.z + ONE_MINUS_DECAY * (en.z - e.z),
                    e.w + ONE_MINUS_DECAY * (en.w - e.w));

    if (t == 0) {
        float cs = cluster_size[c];
        out_cs[c] = cs + ONE_MINUS_DECAY * (b - cs);
    }
}

// ============================================================================
extern "C" void kernel_launch(void* const* d_in, const int* in_sizes, int n_in,
                              void* d_out, int out_size) {
    const float* x     = (const float*)d_in[0];
    const float* embed = (const float*)d_in[1];
    const float* cs    = (const float*)d_in[2];

    float* out       = (float*)d_out;
    float* out_q     = out;
    float* out_ind   = out + 16777216;
    float* out_embed = out + 16777216 + 32768;
    float* out_cs    = out + 16777216 + 32768 + 4194304;

    norm_embed_kernel<<<C_CODES, 128>>>(embed);
    norm_x_kernel<<<N_TOK, 128>>>(x);
    argmax_kernel<<<N_TOK / BM, 256>>>();
    epilogue_kernel<<<N_TOK, 128>>>(embed, out_q, out_ind);
    finalize_kernel<<<C_CODES, 128>>>(embed, cs, out_embed, out_cs);
}